// round 7
// baseline (speedup 1.0000x reference)
#include <cuda_runtime.h>
#include <cuda_bf16.h>
#include <cstddef>
#include <cstdint>

#define HDIM 1024
#define SLEN 4096
#define BATCH 32
#define NSB 8                              // s-blocks per batch = cluster size
#define ROWS_PER_BLOCK (SLEN / NSB)        // 512
#define NWARPS 8
#define ROWS_PER_WARP (ROWS_PER_BLOCK / NWARPS)  // 64
#define VCHUNKS 64                         // o-chunks for vprime

// Scratch (device globals; no allocation in kernel_launch)
__device__ float g_vpart[VCHUNKS][HDIM];           // partial U^T V
__device__ float g_vprime[HDIM];                   // reduced U^T V

// ---------------- DSMEM / cluster helpers ----------------
__device__ __forceinline__ uint32_t smem_u32(const void* p) {
    return (uint32_t)__cvta_generic_to_shared(p);
}
__device__ __forceinline__ uint32_t mapa_rank(uint32_t addr, uint32_t rank) {
    uint32_t r;
    asm("mapa.shared::cluster.u32 %0, %1, %2;" : "=r"(r) : "r"(addr), "r"(rank));
    return r;
}
__device__ __forceinline__ float2 ld_dsmem_f2(uint32_t a) {
    float2 v;
    asm volatile("ld.shared::cluster.v2.f32 {%0,%1}, [%2];"
                 : "=f"(v.x), "=f"(v.y) : "r"(a));
    return v;
}
__device__ __forceinline__ float4 ld_dsmem_f4(uint32_t a) {
    float4 v;
    asm volatile("ld.shared::cluster.v4.f32 {%0,%1,%2,%3}, [%4];"
                 : "=f"(v.x), "=f"(v.y), "=f"(v.z), "=f"(v.w) : "r"(a));
    return v;
}
#define CLUSTER_SYNC() do { \
    asm volatile("barrier.cluster.arrive.aligned;" ::: "memory"); \
    asm volatile("barrier.cluster.wait.aligned;" ::: "memory"); \
} while (0)

// ---------------------------------------------------------------------------
// K1: v' partials, float2 per thread. grid (4, 64), block 128.
// ---------------------------------------------------------------------------
__global__ void vprime_kernel(const float* __restrict__ U,
                              const float* __restrict__ V) {
    const int h2 = blockIdx.x * 128 + threadIdx.x;   // float2 index, 512 total
    const int oc = blockIdx.y;
    const int o0 = oc * (HDIM / VCHUNKS);
    const float2* __restrict__ U2 = reinterpret_cast<const float2*>(U);
    float2 acc = make_float2(0.f, 0.f);
#pragma unroll
    for (int o = 0; o < HDIM / VCHUNKS; o++) {       // 16, fully unrolled
        float2 u = __ldcs(U2 + (size_t)(o0 + o) * (HDIM / 2) + h2);
        const float v = V[o0 + o];
        acc.x += u.x * v; acc.y += u.y * v;
    }
    reinterpret_cast<float2*>(g_vpart[oc])[h2] = acc;
}

// K1b: reduce the 64 partials. grid 8, block 128.
__global__ void vreduce_kernel() {
    const int h = blockIdx.x * 128 + threadIdx.x;
    float a = 0.0f;
#pragma unroll
    for (int oc = 0; oc < VCHUNKS; oc++) a += g_vpart[oc][h];
    g_vprime[h] = a;
}

// ---------------------------------------------------------------------------
// K2: fused streaming pass (keys read once, __ldcs) + cluster epilogue.
// v' lives in SMEM (frees 32 regs); key rows are software-pipelined 2-deep
// so next-row loads overlap the serial dot/shfl/exp section.
// grid (NSB, BATCH), cluster (NSB,1,1), block 256, occ 2.
// out layout: [context B*H | weight B*S]
// ---------------------------------------------------------------------------
struct OnlineState {
    float m, l;
    float4 acc[8];
};

__device__ __forceinline__ void process_row(
    const float4 (&k)[8], const float4* __restrict__ svp,
    float* __restrict__ score_slot, OnlineState& st, int lane)
{
    float d = 0.0f;
#pragma unroll
    for (int i = 0; i < 8; i++) {
        float4 vp = svp[i * 32];
        d += k[i].x * vp.x + k[i].y * vp.y + k[i].z * vp.z + k[i].w * vp.w;
    }
#pragma unroll
    for (int off = 16; off; off >>= 1)
        d += __shfl_xor_sync(0xffffffffu, d, off);

    if (lane == 0) *score_slot = d;

    if (d > st.m) {  // warp-uniform
        float sc = __expf(st.m - d);
        st.l *= sc;
#pragma unroll
        for (int i = 0; i < 8; i++) {
            st.acc[i].x *= sc; st.acc[i].y *= sc;
            st.acc[i].z *= sc; st.acc[i].w *= sc;
        }
        st.m = d;
    }
    float p = __expf(d - st.m);
    st.l += p;
#pragma unroll
    for (int i = 0; i < 8; i++) {
        st.acc[i].x += p * k[i].x; st.acc[i].y += p * k[i].y;
        st.acc[i].z += p * k[i].z; st.acc[i].w += p * k[i].w;
    }
}

__global__ void __launch_bounds__(256, 2) __cluster_dims__(NSB, 1, 1)
main_pass_kernel(const float* __restrict__ keys, float* __restrict__ out) {
    const int b    = blockIdx.y;
    const int sb   = blockIdx.x;          // == cluster rank
    const int w    = threadIdx.x >> 5;
    const int lane = threadIdx.x & 31;
    const int t    = threadIdx.x;

    __shared__ float4 s_vp[256];               // 4 KB v'
    __shared__ float4 s_acc[NWARPS][256];      // 32 KB warp partials
    __shared__ float  s_m[NWARPS];
    __shared__ float  s_l[NWARPS];
    __shared__ float4 s_bacc[256];             // 4 KB block partial acc
    __shared__ float2 s_ml;                    // block partial (M, L)
    __shared__ float  s_scores[ROWS_PER_BLOCK];// 2 KB raw scores
    __shared__ float  s_pm[NSB], s_pl[NSB];    // gathered peer M/L

    s_vp[t] = reinterpret_cast<const float4*>(g_vprime)[t];
    __syncthreads();

    OnlineState st;
    st.m = -3.0e38f;
    st.l = 0.0f;
#pragma unroll
    for (int i = 0; i < 8; i++) st.acc[i] = make_float4(0.f, 0.f, 0.f, 0.f);

    const int s0 = sb * ROWS_PER_BLOCK + w * ROWS_PER_WARP;
    const float4* __restrict__ base =
        reinterpret_cast<const float4*>(keys + (size_t)b * SLEN * HDIM)
        + (size_t)s0 * (HDIM / 4) + lane;
    const float4* __restrict__ svp = &s_vp[lane];
    float* __restrict__ w_scores = &s_scores[w * ROWS_PER_WARP];

    float4 ka[8], kb[8];
#pragma unroll
    for (int i = 0; i < 8; i++) ka[i] = __ldcs(base + i * 32);

    for (int j = 0; j < ROWS_PER_WARP; j += 2) {
        const float4* __restrict__ r1 = base + (size_t)(j + 1) * (HDIM / 4);
#pragma unroll
        for (int i = 0; i < 8; i++) kb[i] = __ldcs(r1 + i * 32);

        process_row(ka, svp, w_scores + j, st, lane);

        if (j + 2 < ROWS_PER_WARP) {
            const float4* __restrict__ r2 = base + (size_t)(j + 2) * (HDIM / 4);
#pragma unroll
            for (int i = 0; i < 8; i++) ka[i] = __ldcs(r2 + i * 32);
        }

        process_row(kb, svp, w_scores + j + 1, st, lane);
    }

    // ---- block-level merge of 8 warp partials (smem) ----
#pragma unroll
    for (int i = 0; i < 8; i++) s_acc[w][i * 32 + lane] = st.acc[i];
    if (lane == 0) { s_m[w] = st.m; s_l[w] = st.l; }
    __syncthreads();

    float Mb = s_m[0];
#pragma unroll
    for (int ww = 1; ww < NWARPS; ww++) Mb = fmaxf(Mb, s_m[ww]);
    float Lb = 0.0f;
    float scale[NWARPS];
#pragma unroll
    for (int ww = 0; ww < NWARPS; ww++) {
        scale[ww] = __expf(s_m[ww] - Mb);
        Lb += scale[ww] * s_l[ww];
    }

    float4 bsum = make_float4(0.f, 0.f, 0.f, 0.f);
#pragma unroll
    for (int ww = 0; ww < NWARPS; ww++) {
        float4 v = s_acc[ww][t];
        const float sc = scale[ww];
        bsum.x += sc * v.x; bsum.y += sc * v.y;
        bsum.z += sc * v.z; bsum.w += sc * v.w;
    }
    s_bacc[t] = bsum;
    if (t == 0) { s_ml.x = Mb; s_ml.y = Lb; }
    __syncthreads();

    // ---- cluster-wide merge via DSMEM ----
    CLUSTER_SYNC();

    if (t < NSB) {
        uint32_t a = mapa_rank(smem_u32(&s_ml), (uint32_t)t);
        float2 ml = ld_dsmem_f2(a);
        s_pm[t] = ml.x; s_pl[t] = ml.y;
    }
    __syncthreads();

    float M = s_pm[0];
#pragma unroll
    for (int p = 1; p < NSB; p++) M = fmaxf(M, s_pm[p]);
    float L = 0.0f;
    float scg[NSB];
#pragma unroll
    for (int p = 0; p < NSB; p++) {
        scg[p] = __expf(s_pm[p] - M);
        L += scg[p] * s_pl[p];
    }
    const float invL = 1.0f / L;

    // context slice: this CTA owns float4 columns [sb*32, sb*32+32)
    if (t < 32) {
        const int h4 = sb * 32 + t;
        const uint32_t loc = smem_u32(&s_bacc[h4]);
        float4 cs = make_float4(0.f, 0.f, 0.f, 0.f);
#pragma unroll
        for (int p = 0; p < NSB; p++) {
            float4 v = ld_dsmem_f4(mapa_rank(loc, (uint32_t)p));
            cs.x += scg[p] * v.x; cs.y += scg[p] * v.y;
            cs.z += scg[p] * v.z; cs.w += scg[p] * v.w;
        }
        cs.x *= invL; cs.y *= invL; cs.z *= invL; cs.w *= invL;
        reinterpret_cast<float4*>(out + (size_t)b * HDIM)[h4] = cs;
    }

    // weights for this CTA's 512 rows
    float* __restrict__ wout =
        out + (size_t)BATCH * HDIM + (size_t)b * SLEN + (size_t)sb * ROWS_PER_BLOCK;
#pragma unroll
    for (int i = 0; i < ROWS_PER_BLOCK / 256; i++) {
        const int s = i * 256 + t;
        wout[s] = __expf(s_scores[s] - M) * invL;
    }

    // protect SMEM until all peers finished their DSMEM reads
    CLUSTER_SYNC();
}

// ---------------------------------------------------------------------------
extern "C" void kernel_launch(void* const* d_in, const int* in_sizes, int n_in,
                              void* d_out, int out_size) {
    // inputs (metadata order): query, keys, W, U, V
    const float* keys = (const float*)d_in[1];
    const float* U    = (const float*)d_in[3];
    const float* V    = (const float*)d_in[4];
    float* out = (float*)d_out;

    vprime_kernel<<<dim3(4, VCHUNKS), 128>>>(U, V);
    vreduce_kernel<<<8, 128>>>();
    main_pass_kernel<<<dim3(NSB, BATCH), 256>>>(keys, out);
}

// round 8
// speedup vs baseline: 1.2097x; 1.2097x over previous
#include <cuda_runtime.h>
#include <cuda_bf16.h>
#include <cstddef>
#include <cstdint>

#define HDIM 1024
#define SLEN 4096
#define BATCH 32
#define NSB 8                              // s-blocks per batch = cluster size
#define ROWS_PER_BLOCK (SLEN / NSB)        // 512
#define NWARPS 8
#define ROWS_PER_WARP (ROWS_PER_BLOCK / NWARPS)  // 64
#define HALF_RPW (ROWS_PER_WARP / 2)       // 32
#define VCHUNKS 64                         // o-chunks for vprime

// Scratch (device globals; no allocation in kernel_launch)
__device__ float g_vpart[VCHUNKS][HDIM];           // partial U^T V
__device__ float g_vprime[HDIM];                   // reduced U^T V

// ---------------- smem / cluster helpers ----------------
__device__ __forceinline__ uint32_t smem_u32(const void* p) {
    return (uint32_t)__cvta_generic_to_shared(p);
}
__device__ __forceinline__ uint32_t mapa_rank(uint32_t addr, uint32_t rank) {
    uint32_t r;
    asm("mapa.shared::cluster.u32 %0, %1, %2;" : "=r"(r) : "r"(addr), "r"(rank));
    return r;
}
__device__ __forceinline__ float2 ld_dsmem_f2(uint32_t a) {
    float2 v;
    asm volatile("ld.shared::cluster.v2.f32 {%0,%1}, [%2];"
                 : "=f"(v.x), "=f"(v.y) : "r"(a));
    return v;
}
__device__ __forceinline__ float4 ld_dsmem_f4(uint32_t a) {
    float4 v;
    asm volatile("ld.shared::cluster.v4.f32 {%0,%1,%2,%3}, [%4];"
                 : "=f"(v.x), "=f"(v.y), "=f"(v.z), "=f"(v.w) : "r"(a));
    return v;
}
// volatile LDS.128: cannot be hoisted out of the loop by the compiler
__device__ __forceinline__ float4 lds_f4(uint32_t a) {
    float4 v;
    asm volatile("ld.shared.v4.f32 {%0,%1,%2,%3}, [%4];"
                 : "=f"(v.x), "=f"(v.y), "=f"(v.z), "=f"(v.w) : "r"(a));
    return v;
}
#define CLUSTER_SYNC() do { \
    asm volatile("barrier.cluster.arrive.aligned;" ::: "memory"); \
    asm volatile("barrier.cluster.wait.aligned;" ::: "memory"); \
} while (0)

// ---------------------------------------------------------------------------
// K1: v' partials. grid (8, 64), block 128.  (R6 variant — measured 5.2us)
// ---------------------------------------------------------------------------
__global__ void vprime_kernel(const float* __restrict__ U,
                              const float* __restrict__ V) {
    const int h  = blockIdx.x * 128 + threadIdx.x;
    const int oc = blockIdx.y;
    const int o0 = oc * (HDIM / VCHUNKS);
    float acc = 0.0f;
#pragma unroll
    for (int o = 0; o < HDIM / VCHUNKS; o++) {      // 16, fully unrolled
        acc += U[(size_t)(o0 + o) * HDIM + h] * V[o0 + o];
    }
    g_vpart[oc][h] = acc;
}

// K1b: reduce the 64 partials. grid 8, block 128.
__global__ void vreduce_kernel() {
    const int h = blockIdx.x * 128 + threadIdx.x;
    float a = 0.0f;
#pragma unroll
    for (int oc = 0; oc < VCHUNKS; oc++) a += g_vpart[oc][h];
    g_vprime[h] = a;
}

// ---------------------------------------------------------------------------
// K2: fused streaming pass (keys read once, __ldcs) + cluster epilogue.
// Row-pair interleaving: each warp processes rows j and j+32 together
// (16 front-batched LDG.128, two interleaved shfl-reduce chains).
// v' in SMEM via volatile LDS (no register hoist -> no spills).
// grid (NSB, BATCH), cluster (NSB,1,1), block 256, occ 2.
// out layout: [context B*H | weight B*S]
// ---------------------------------------------------------------------------
__global__ void __launch_bounds__(256, 2) __cluster_dims__(NSB, 1, 1)
main_pass_kernel(const float* __restrict__ keys, float* __restrict__ out) {
    const int b    = blockIdx.y;
    const int sb   = blockIdx.x;          // == cluster rank
    const int w    = threadIdx.x >> 5;
    const int lane = threadIdx.x & 31;
    const int t    = threadIdx.x;

    __shared__ float4 s_vp[256];               // 4 KB v'
    __shared__ float4 s_acc[NWARPS][256];      // 32 KB warp partials
    __shared__ float  s_m[NWARPS];
    __shared__ float  s_l[NWARPS];
    __shared__ float4 s_bacc[256];             // 4 KB block partial acc
    __shared__ float2 s_ml;                    // block partial (M, L)
    __shared__ float  s_scores[ROWS_PER_BLOCK];// 2 KB raw scores
    __shared__ float  s_pm[NSB], s_pl[NSB];    // gathered peer M/L

    s_vp[t] = reinterpret_cast<const float4*>(g_vprime)[t];
    __syncthreads();

    float m = -3.0e38f;
    float l = 0.0f;
    float4 acc[8];
#pragma unroll
    for (int i = 0; i < 8; i++) acc[i] = make_float4(0.f, 0.f, 0.f, 0.f);

    const int s0 = sb * ROWS_PER_BLOCK + w * ROWS_PER_WARP;
    const float4* __restrict__ base =
        reinterpret_cast<const float4*>(keys + (size_t)b * SLEN * HDIM)
        + (size_t)s0 * (HDIM / 4) + lane;
    const uint32_t vp_base = smem_u32(&s_vp[lane]);   // +i*32*16 per step
    float* __restrict__ w_scores = &s_scores[w * ROWS_PER_WARP];

    for (int j = 0; j < HALF_RPW; j++) {
        const float4* __restrict__ rA = base + (size_t)j * (HDIM / 4);
        const float4* __restrict__ rB = rA + (size_t)HALF_RPW * (HDIM / 4);

        float4 k1[8], k2[8];
#pragma unroll
        for (int i = 0; i < 8; i++) k1[i] = __ldcs(rA + i * 32);
#pragma unroll
        for (int i = 0; i < 8; i++) k2[i] = __ldcs(rB + i * 32);

        float d1 = 0.0f, d2 = 0.0f;
#pragma unroll
        for (int i = 0; i < 8; i++) {
            const float4 vp = lds_f4(vp_base + (uint32_t)(i * 32) * 16u);
            d1 += k1[i].x * vp.x + k1[i].y * vp.y +
                  k1[i].z * vp.z + k1[i].w * vp.w;
            d2 += k2[i].x * vp.x + k2[i].y * vp.y +
                  k2[i].z * vp.z + k2[i].w * vp.w;
        }
#pragma unroll
        for (int off = 16; off; off >>= 1) {
            d1 += __shfl_xor_sync(0xffffffffu, d1, off);
            d2 += __shfl_xor_sync(0xffffffffu, d2, off);
        }

        if (lane == 0) {
            w_scores[j]            = d1;
            w_scores[j + HALF_RPW] = d2;
        }

        const float mNew = fmaxf(m, fmaxf(d1, d2));
        if (mNew > m) {           // warp-uniform, rare
            const float sc = __expf(m - mNew);
            l *= sc;
#pragma unroll
            for (int i = 0; i < 8; i++) {
                acc[i].x *= sc; acc[i].y *= sc;
                acc[i].z *= sc; acc[i].w *= sc;
            }
            m = mNew;
        }
        const float p1 = __expf(d1 - m);
        const float p2 = __expf(d2 - m);
        l += p1 + p2;
#pragma unroll
        for (int i = 0; i < 8; i++) {
            acc[i].x += p1 * k1[i].x + p2 * k2[i].x;
            acc[i].y += p1 * k1[i].y + p2 * k2[i].y;
            acc[i].z += p1 * k1[i].z + p2 * k2[i].z;
            acc[i].w += p1 * k1[i].w + p2 * k2[i].w;
        }
    }

    // ---- block-level merge of 8 warp partials (smem) ----
#pragma unroll
    for (int i = 0; i < 8; i++) s_acc[w][i * 32 + lane] = acc[i];
    if (lane == 0) { s_m[w] = m; s_l[w] = l; }
    __syncthreads();

    float Mb = s_m[0];
#pragma unroll
    for (int ww = 1; ww < NWARPS; ww++) Mb = fmaxf(Mb, s_m[ww]);
    float Lb = 0.0f;
    float scale[NWARPS];
#pragma unroll
    for (int ww = 0; ww < NWARPS; ww++) {
        scale[ww] = __expf(s_m[ww] - Mb);
        Lb += scale[ww] * s_l[ww];
    }

    float4 bsum = make_float4(0.f, 0.f, 0.f, 0.f);
#pragma unroll
    for (int ww = 0; ww < NWARPS; ww++) {
        float4 v = s_acc[ww][t];
        const float sc = scale[ww];
        bsum.x += sc * v.x; bsum.y += sc * v.y;
        bsum.z += sc * v.z; bsum.w += sc * v.w;
    }
    s_bacc[t] = bsum;
    if (t == 0) { s_ml.x = Mb; s_ml.y = Lb; }
    __syncthreads();

    // ---- cluster-wide merge via DSMEM ----
    CLUSTER_SYNC();

    if (t < NSB) {
        uint32_t a = mapa_rank(smem_u32(&s_ml), (uint32_t)t);
        float2 ml = ld_dsmem_f2(a);
        s_pm[t] = ml.x; s_pl[t] = ml.y;
    }
    __syncthreads();

    float M = s_pm[0];
#pragma unroll
    for (int p = 1; p < NSB; p++) M = fmaxf(M, s_pm[p]);
    float L = 0.0f;
    float scg[NSB];
#pragma unroll
    for (int p = 0; p < NSB; p++) {
        scg[p] = __expf(s_pm[p] - M);
        L += scg[p] * s_pl[p];
    }
    const float invL = 1.0f / L;

    // context slice: this CTA owns float4 columns [sb*32, sb*32+32)
    if (t < 32) {
        const int h4 = sb * 32 + t;
        const uint32_t loc = smem_u32(&s_bacc[h4]);
        float4 cs = make_float4(0.f, 0.f, 0.f, 0.f);
#pragma unroll
        for (int p = 0; p < NSB; p++) {
            float4 v = ld_dsmem_f4(mapa_rank(loc, (uint32_t)p));
            cs.x += scg[p] * v.x; cs.y += scg[p] * v.y;
            cs.z += scg[p] * v.z; cs.w += scg[p] * v.w;
        }
        cs.x *= invL; cs.y *= invL; cs.z *= invL; cs.w *= invL;
        reinterpret_cast<float4*>(out + (size_t)b * HDIM)[h4] = cs;
    }

    // weights for this CTA's 512 rows
    float* __restrict__ wout =
        out + (size_t)BATCH * HDIM + (size_t)b * SLEN + (size_t)sb * ROWS_PER_BLOCK;
#pragma unroll
    for (int i = 0; i < ROWS_PER_BLOCK / 256; i++) {
        const int s = i * 256 + t;
        wout[s] = __expf(s_scores[s] - M) * invL;
    }

    // protect SMEM until all peers finished their DSMEM reads
    CLUSTER_SYNC();
}

// ---------------------------------------------------------------------------
extern "C" void kernel_launch(void* const* d_in, const int* in_sizes, int n_in,
                              void* d_out, int out_size) {
    // inputs (metadata order): query, keys, W, U, V
    const float* keys = (const float*)d_in[1];
    const float* U    = (const float*)d_in[3];
    const float* V    = (const float*)d_in[4];
    float* out = (float*)d_out;

    vprime_kernel<<<dim3(8, VCHUNKS), 128>>>(U, V);
    vreduce_kernel<<<8, 128>>>();
    main_pass_kernel<<<dim3(NSB, BATCH), 256>>>(keys, out);
}